// round 5
// baseline (speedup 1.0000x reference)
#include <cuda_runtime.h>
#include <cuda_bf16.h>
#include <cstdint>

#define NV 8192
#define NC 128

// -------------------- device scratch (no allocs allowed) --------------------
__device__ __nv_bfloat16 g_Ehi[(size_t)NV * NV];   // 128 MB
__device__ __nv_bfloat16 g_Elo[(size_t)NV * NV];   // 128 MB
__device__ __nv_bfloat16 g_xh[NV * NC];
__device__ __nv_bfloat16 g_xl[NV * NC];
__device__ __nv_bfloat16 g_yh[NV * NC];
__device__ __nv_bfloat16 g_yl[NV * NC];
__device__ float g_E0[64 * NC];
__device__ float g_E1[128 * NC];

// -------------------- small kernels ------------------------------------------
__global__ void coef_kernel(const float* __restrict__ ev0,
                            const float* __restrict__ ev1,
                            const float* __restrict__ dt) {
    int c = threadIdx.x;
    int b = blockIdx.x;
    if (b < 64) g_E0[b * NC + c] = __expf(-ev0[b] * dt[c]);
    else        g_E1[(b - 64) * NC + c] = __expf(-ev1[b - 64] * dt[NC + c]);
}

__device__ __forceinline__ uint32_t pack_bf2(__nv_bfloat16 a, __nv_bfloat16 b) {
    __nv_bfloat162 p{a, b};
    return *(uint32_t*)&p;
}

__global__ void __launch_bounds__(256) convE_kernel(const float4* __restrict__ E4,
                                                    uint2* __restrict__ Eh,
                                                    uint2* __restrict__ El) {
    const size_t N4 = (size_t)NV * NV / 4;
    for (size_t idx = (size_t)blockIdx.x * 256 + threadIdx.x; idx < N4;
         idx += (size_t)gridDim.x * 256) {
        float4 v = E4[idx];
        __nv_bfloat16 h0 = __float2bfloat16(v.x), h1 = __float2bfloat16(v.y);
        __nv_bfloat16 h2 = __float2bfloat16(v.z), h3 = __float2bfloat16(v.w);
        __nv_bfloat16 l0 = __float2bfloat16(v.x - __bfloat162float(h0));
        __nv_bfloat16 l1 = __float2bfloat16(v.y - __bfloat162float(h1));
        __nv_bfloat16 l2 = __float2bfloat16(v.z - __bfloat162float(h2));
        __nv_bfloat16 l3 = __float2bfloat16(v.w - __bfloat162float(h3));
        Eh[idx] = make_uint2(pack_bf2(h0, h1), pack_bf2(h2, h3));
        El[idx] = make_uint2(pack_bf2(l0, l1), pack_bf2(l2, l3));
    }
}

__global__ void __launch_bounds__(256) prepx_kernel(const float4* __restrict__ x4,
                                                    const float* __restrict__ mass,
                                                    uint2* __restrict__ xh,
                                                    uint2* __restrict__ xl) {
    int idx = blockIdx.x * 256 + threadIdx.x;
    float m = mass[(idx * 4) >> 7];
    float4 v = x4[idx];
    float a = v.x * m, b = v.y * m, c = v.z * m, d = v.w * m;
    __nv_bfloat16 h0 = __float2bfloat16(a), h1 = __float2bfloat16(b);
    __nv_bfloat16 h2 = __float2bfloat16(c), h3 = __float2bfloat16(d);
    __nv_bfloat16 l0 = __float2bfloat16(a - __bfloat162float(h0));
    __nv_bfloat16 l1 = __float2bfloat16(b - __bfloat162float(h1));
    __nv_bfloat16 l2 = __float2bfloat16(c - __bfloat162float(h2));
    __nv_bfloat16 l3 = __float2bfloat16(d - __bfloat162float(h3));
    xh[idx] = make_uint2(pack_bf2(h0, h1), pack_bf2(h2, h3));
    xl[idx] = make_uint2(pack_bf2(l0, l1), pack_bf2(l2, l3));
}

// -------------------- mma.sync helpers ----------------------------------------
__device__ __forceinline__ void ldsm4(uint32_t* r, uint32_t addr) {
    asm volatile("ldmatrix.sync.aligned.m8n8.x4.shared.b16 {%0,%1,%2,%3}, [%4];"
                 : "=r"(r[0]), "=r"(r[1]), "=r"(r[2]), "=r"(r[3]) : "r"(addr));
}
__device__ __forceinline__ void ldsm4t(uint32_t* r, uint32_t addr) {
    asm volatile("ldmatrix.sync.aligned.m8n8.x4.trans.shared.b16 {%0,%1,%2,%3}, [%4];"
                 : "=r"(r[0]), "=r"(r[1]), "=r"(r[2]), "=r"(r[3]) : "r"(addr));
}
__device__ __forceinline__ void mma16816(float* d, const uint32_t* a, const uint32_t* b) {
    asm volatile("mma.sync.aligned.m16n8k16.row.col.f32.bf16.bf16.f32 "
                 "{%0,%1,%2,%3}, {%4,%5,%6,%7}, {%8,%9}, {%0,%1,%2,%3};"
                 : "+f"(d[0]), "+f"(d[1]), "+f"(d[2]), "+f"(d[3])
                 : "r"(a[0]), "r"(a[1]), "r"(a[2]), "r"(a[3]),
                   "r"(b[0]), "r"(b[1]));
}
#define CP16(dst, src) \
    asm volatile("cp.async.cg.shared.global [%0], [%1], 16;" :: "r"(dst), "l"(src) : "memory")

// -------------------- GEMM config ----------------------------------------------
#define BM 64
#define BN 128
#define BK 64
#define APAD 72
#define BPAD 136
#define A_HALVES (BK * APAD)
#define B_HALVES (BK * BPAD)
#define A_BYTES  (A_HALVES * 2)      // 9216
#define B_BYTES  (B_HALVES * 2)      // 17408
#define STAGE_BYTES (2 * A_BYTES + 2 * B_BYTES)   // 53248
#define NSTAGE 4
#define SMEM_BYTES (NSTAGE * STAGE_BYTES)         // 212992

// C[m,n] = sum_k Aop[m,k]*B[k,n]; bf16 hi/lo 3-term split.
template <int TRANS_A, int EPI>
__global__ void __launch_bounds__(256, 1)
gemm_kernel(const __nv_bfloat16* __restrict__ Ahi, const __nv_bfloat16* __restrict__ Alo,
            const __nv_bfloat16* __restrict__ Bhi, const __nv_bfloat16* __restrict__ Blo,
            float* __restrict__ C,
            __nv_bfloat16* __restrict__ yhi, __nv_bfloat16* __restrict__ ylo,
            const float* __restrict__ E0, const float* __restrict__ E1)
{
    extern __shared__ __nv_bfloat16 sm[];
    const uint32_t smbase = (uint32_t)__cvta_generic_to_shared(sm);
    const int tid  = threadIdx.x;
    const int lane = tid & 31, wid = tid >> 5;
    const int wm   = wid >> 2, wn = wid & 3;      // 2 x 4 warp grid (32x32 tiles)
    const int m0   = blockIdx.x * BM;

    auto issue = [&](int kt, int s) {
        const int k0 = kt * BK;
        const uint32_t sb = smbase + s * STAGE_BYTES;
#pragma unroll
        for (int i = 0; i < 2; i++) {
            int idx = i * 256 + tid;
            int r = idx >> 3, q = idx & 7;
            size_t ga = TRANS_A ? (size_t)(k0 + r) * NV + m0 + q * 8
                                : (size_t)(m0 + r) * NV + k0 + q * 8;
            uint32_t so = sb + (uint32_t)(r * APAD + q * 8) * 2;
            CP16(so, (const void*)(Ahi + ga));
            CP16(so + A_BYTES, (const void*)(Alo + ga));
        }
#pragma unroll
        for (int i = 0; i < 4; i++) {
            int idx = i * 256 + tid;
            int r = idx >> 4, q = idx & 15;
            size_t gb = (size_t)(k0 + r) * NC + q * 8;
            uint32_t so = sb + 2 * A_BYTES + (uint32_t)(r * BPAD + q * 8) * 2;
            CP16(so, (const void*)(Bhi + gb));
            CP16(so + B_BYTES, (const void*)(Blo + gb));
        }
        asm volatile("cp.async.commit_group;" ::: "memory");
    };

    float acc[2][4][4];
#pragma unroll
    for (int a = 0; a < 2; a++)
#pragma unroll
        for (int b = 0; b < 4; b++)
#pragma unroll
            for (int q = 0; q < 4; q++) acc[a][b][q] = 0.0f;

    // fragment double buffers (buf = ks & 1)
    uint32_t ah[2][2][4], al[2][2][4], bh[2][2][4], bl[2][2][4];

    // per-thread invariant ldmatrix offsets
    int a_row, a_col, b_row, b_col;
    if (TRANS_A) { a_row = (lane & 7) + ((lane >> 4) << 3); a_col = wm * 32 + (lane & 8); }
    else         { a_row = wm * 32 + (lane & 15);           a_col = ((lane >> 4) << 3);   }
    b_row = lane & 15;
    b_col = wn * 32 + ((lane >> 4) << 3);

    auto ldfrag = [&](uint32_t stage_base, int ks, int buf) {
        const uint32_t Ahb = stage_base;
        const uint32_t Bhb = stage_base + 2 * A_BYTES;
#pragma unroll
        for (int mi = 0; mi < 2; mi++) {
            uint32_t addr;
            if (TRANS_A) {
                addr = Ahb + (uint32_t)((ks * 16 + a_row) * APAD + a_col + mi * 16) * 2;
                ldsm4t(ah[buf][mi], addr);
                ldsm4t(al[buf][mi], addr + A_BYTES);
            } else {
                addr = Ahb + (uint32_t)((a_row + mi * 16) * APAD + ks * 16 + a_col) * 2;
                ldsm4(ah[buf][mi], addr);
                ldsm4(al[buf][mi], addr + A_BYTES);
            }
        }
#pragma unroll
        for (int nj2 = 0; nj2 < 2; nj2++) {
            uint32_t addr = Bhb + (uint32_t)((ks * 16 + b_row) * BPAD + b_col + nj2 * 16) * 2;
            ldsm4t(bh[buf][nj2], addr);
            ldsm4t(bl[buf][nj2], addr + B_BYTES);
        }
    };

    // term-major MMA burst: 3 sweeps of 8 independent accumulators
    auto mma_burst = [&](int buf) {
#pragma unroll
        for (int mi = 0; mi < 2; mi++)
#pragma unroll
            for (int nj = 0; nj < 4; nj++)
                mma16816(acc[mi][nj], ah[buf][mi], &bh[buf][nj >> 1][(nj & 1) * 2]);
#pragma unroll
        for (int mi = 0; mi < 2; mi++)
#pragma unroll
            for (int nj = 0; nj < 4; nj++)
                mma16816(acc[mi][nj], ah[buf][mi], &bl[buf][nj >> 1][(nj & 1) * 2]);
#pragma unroll
        for (int mi = 0; mi < 2; mi++)
#pragma unroll
            for (int nj = 0; nj < 4; nj++)
                mma16816(acc[mi][nj], al[buf][mi], &bh[buf][nj >> 1][(nj & 1) * 2]);
    };

    const int NIT = NV / BK;   // 128
    issue(0, 0); issue(1, 1); issue(2, 2);
    asm volatile("cp.async.wait_group 1;" ::: "memory");   // stages 0,1 complete
    __syncthreads();
    ldfrag(smbase + 0 * STAGE_BYTES, 0, 0);

#pragma unroll 1
    for (int kt = 0; kt < NIT; kt++) {
        const uint32_t cur = smbase + (kt % NSTAGE) * STAGE_BYTES;
        const int ktn = (kt + 1 < NIT) ? kt + 1 : kt;        // cross-tile prefetch src
        const uint32_t nxt = smbase + (ktn % NSTAGE) * STAGE_BYTES;
#pragma unroll
        for (int ks = 0; ks < 4; ks++) {
            if (ks < 3) ldfrag(cur, ks + 1, (ks + 1) & 1);
            else        ldfrag(nxt, 0, (ks + 1) & 1);        // next tile, kstep 0
            mma_burst(ks & 1);
        }
        if (kt + 3 < NIT) issue(kt + 3, (kt + 3) % NSTAGE);
        asm volatile("cp.async.wait_group 1;" ::: "memory"); // stage kt+2 complete
        __syncthreads();
    }

    // ---- epilogue ----
#pragma unroll
    for (int mi = 0; mi < 2; mi++) {
#pragma unroll
        for (int q = 0; q < 2; q++) {
            int gm = m0 + wm * 32 + mi * 16 + (lane >> 2) + q * 8;
            int i0 = gm >> 7, i1 = gm & 127;
#pragma unroll
            for (int nj = 0; nj < 4; nj++) {
                int gn = wn * 32 + nj * 8 + (lane & 3) * 2;
                float v0 = acc[mi][nj][q * 2 + 0];
                float v1 = acc[mi][nj][q * 2 + 1];
                if (EPI) {
                    v0 *= E0[i0 * NC + gn]     * E1[i1 * NC + gn];
                    v1 *= E0[i0 * NC + gn + 1] * E1[i1 * NC + gn + 1];
                    __nv_bfloat16 h0 = __float2bfloat16(v0);
                    __nv_bfloat16 h1 = __float2bfloat16(v1);
                    __nv_bfloat16 l0 = __float2bfloat16(v0 - __bfloat162float(h0));
                    __nv_bfloat16 l1 = __float2bfloat16(v1 - __bfloat162float(h1));
                    *(uint32_t*)&yhi[(size_t)gm * NC + gn] = pack_bf2(h0, h1);
                    *(uint32_t*)&ylo[(size_t)gm * NC + gn] = pack_bf2(l0, l1);
                } else {
                    *(float2*)&C[(size_t)gm * NC + gn] = make_float2(v0, v1);
                }
            }
        }
    }
}

// -------------------- launch -----------------------------------------------------
extern "C" void kernel_launch(void* const* d_in, const int* in_sizes, int n_in,
                              void* d_out, int out_size) {
    const float* x      = (const float*)d_in[0];
    const float* mass   = (const float*)d_in[3];
    const float* evals0 = (const float*)d_in[4];
    const float* evals1 = (const float*)d_in[5];
    const float* evecs  = (const float*)d_in[6];
    const float* dt     = (const float*)d_in[7];
    float* out          = (float*)d_out;

    __nv_bfloat16 *Eh, *El, *xh, *xl, *yh, *yl;
    float *E0, *E1;
    cudaGetSymbolAddress((void**)&Eh, g_Ehi);
    cudaGetSymbolAddress((void**)&El, g_Elo);
    cudaGetSymbolAddress((void**)&xh, g_xh);
    cudaGetSymbolAddress((void**)&xl, g_xl);
    cudaGetSymbolAddress((void**)&yh, g_yh);
    cudaGetSymbolAddress((void**)&yl, g_yl);
    cudaGetSymbolAddress((void**)&E0, g_E0);
    cudaGetSymbolAddress((void**)&E1, g_E1);

    cudaFuncSetAttribute(gemm_kernel<1, 1>, cudaFuncAttributeMaxDynamicSharedMemorySize, SMEM_BYTES);
    cudaFuncSetAttribute(gemm_kernel<0, 0>, cudaFuncAttributeMaxDynamicSharedMemorySize, SMEM_BYTES);

    coef_kernel<<<192, 128>>>(evals0, evals1, dt);
    convE_kernel<<<2368, 256>>>((const float4*)evecs, (uint2*)Eh, (uint2*)El);
    prepx_kernel<<<NV * NC / 4 / 256, 256>>>((const float4*)x, mass, (uint2*)xh, (uint2*)xl);

    gemm_kernel<1, 1><<<NV / BM, 256, SMEM_BYTES>>>(Eh, El, xh, xl,
                                                    nullptr, yh, yl, E0, E1);
    gemm_kernel<0, 0><<<NV / BM, 256, SMEM_BYTES>>>(Eh, El, yh, yl,
                                                    out, nullptr, nullptr, nullptr, nullptr);
}